// round 16
// baseline (speedup 1.0000x reference)
#include <cuda_runtime.h>
#include <cuda_bf16.h>
#include <cstdint>
#include <math.h>

// Problem constants
#define BATCH   2
#define SEQ     2048
#define EMB     2048
#define NHEADS  32
#define NGROUPS 8
#define HDIM    64
#define KVDIM   (NGROUPS * HDIM)   // 512
#define ROWS    (BATCH * SEQ)      // 4096
#define GK      2048               // reduction dim for all GEMMs
#define NQKV    (EMB + 2 * KVDIM)  // 3072 fused output columns
#define QMAXI   16256              // 127*128

// ---------------------------------------------------------------------------
// Scratch (no cudaMalloc allowed)
// ---------------------------------------------------------------------------
__device__ float g_V[(size_t)ROWS * KVDIM];      // fp32 V (for transpose)
__device__ float g_A[(size_t)ROWS * EMB];        // fp32 attn output
__device__ float g_Wt[(size_t)NQKV * GK];        // transposed QKV weights fp32
__device__ float g_Wot[(size_t)EMB * GK];        // transposed O weights fp32
__device__ float g_Cp[(size_t)ROWS * NQKV];      // fp32 partial (P11 term)

__device__ __align__(16) int8_t g_xq1[(size_t)ROWS * GK],  g_xq2[(size_t)ROWS * GK];
__device__ __align__(16) int8_t g_wq1[(size_t)NQKV * GK],  g_wq2[(size_t)NQKV * GK];
__device__ __align__(16) int8_t g_woq1[(size_t)EMB * GK],  g_woq2[(size_t)EMB * GK];
__device__ __align__(16) int8_t g_aq1[(size_t)ROWS * GK],  g_aq2[(size_t)ROWS * GK];
__device__ float g_sx[ROWS], g_sw[NQKV], g_swo[EMB], g_sa[ROWS];

// flash operands (bf16 hi/lo, produced by QKV epilogue / vtrans)
__device__ __align__(16) __nv_bfloat16 g_qh[(size_t)ROWS * EMB];
__device__ __align__(16) __nv_bfloat16 g_ql[(size_t)ROWS * EMB];
__device__ __align__(16) __nv_bfloat16 g_kh[(size_t)ROWS * KVDIM];
__device__ __align__(16) __nv_bfloat16 g_kl[(size_t)ROWS * KVDIM];
__device__ __align__(16) __nv_bfloat16 g_vth[(size_t)ROWS * KVDIM];
__device__ __align__(16) __nv_bfloat16 g_vtl[(size_t)ROWS * KVDIM];

// ---------------------------------------------------------------------------
// Primitives
// ---------------------------------------------------------------------------
__device__ __forceinline__ uint32_t smem_u32(const void* p) {
    uint32_t a;
    asm("{ .reg .u64 t; cvta.to.shared.u64 t, %1; cvt.u32.u64 %0, t; }"
        : "=r"(a) : "l"(p));
    return a;
}
__device__ __forceinline__ void ldmx4(uint32_t addr, uint32_t& r0, uint32_t& r1,
                                      uint32_t& r2, uint32_t& r3) {
    asm volatile("ldmatrix.sync.aligned.m8n8.x4.shared.b16 {%0,%1,%2,%3}, [%4];"
                 : "=r"(r0), "=r"(r1), "=r"(r2), "=r"(r3) : "r"(addr));
}
__device__ __forceinline__ void mma16816(float* c, const uint32_t* a,
                                         uint32_t b0, uint32_t b1) {
    asm volatile(
        "mma.sync.aligned.m16n8k16.row.col.f32.bf16.bf16.f32 "
        "{%0,%1,%2,%3}, {%4,%5,%6,%7}, {%8,%9}, {%0,%1,%2,%3};"
        : "+f"(c[0]), "+f"(c[1]), "+f"(c[2]), "+f"(c[3])
        : "r"(a[0]), "r"(a[1]), "r"(a[2]), "r"(a[3]), "r"(b0), "r"(b1));
}
__device__ __forceinline__ void imma16832(int* c, const uint32_t* a,
                                          uint32_t b0, uint32_t b1) {
    asm volatile(
        "mma.sync.aligned.m16n8k32.row.col.s32.s8.s8.s32 "
        "{%0,%1,%2,%3}, {%4,%5,%6,%7}, {%8,%9}, {%0,%1,%2,%3};"
        : "+r"(c[0]), "+r"(c[1]), "+r"(c[2]), "+r"(c[3])
        : "r"(a[0]), "r"(a[1]), "r"(a[2]), "r"(a[3]), "r"(b0), "r"(b1));
}
__device__ __forceinline__ uint32_t packbf(__nv_bfloat16 a, __nv_bfloat16 b) {
    __nv_bfloat162 t = __halves2bfloat162(a, b);
    return *reinterpret_cast<uint32_t*>(&t);
}
__device__ __forceinline__ uint32_t hilo_h(float x, float y) {
    return packbf(__float2bfloat16(x), __float2bfloat16(y));
}
__device__ __forceinline__ uint32_t hilo_l(float x, float y) {
    __nv_bfloat16 hx = __float2bfloat16(x), hy = __float2bfloat16(y);
    return packbf(__float2bfloat16(x - __bfloat162float(hx)),
                  __float2bfloat16(y - __bfloat162float(hy)));
}
__device__ __forceinline__ void cp16(uint32_t dst, const void* src) {
    asm volatile("cp.async.cg.shared.global [%0], [%1], 16;" :: "r"(dst), "l"(src));
}
#define CP_COMMIT() asm volatile("cp.async.commit_group;" ::: "memory")
#define CP_WAIT2()  asm volatile("cp.async.wait_group 2;" ::: "memory")

// ---------------------------------------------------------------------------
// Row-wise 2-digit int8 quantization: x = s*(128*a1 + a2), s = rowmax/16256.
// One block per row of GK=2048, 256 threads x 8 consecutive elements.
// ---------------------------------------------------------------------------
__global__ __launch_bounds__(256)
void quant2(const float* __restrict__ in, int8_t* __restrict__ q1,
            int8_t* __restrict__ q2, float* __restrict__ srow)
{
    const int row = blockIdx.x;
    const int tid = threadIdx.x;
    const float* x = in + (size_t)row * GK + tid * 8;

    float f[8];
    *(float4*)(f)     = *(const float4*)(x);
    *(float4*)(f + 4) = *(const float4*)(x + 4);

    float mx = 0.0f;
#pragma unroll
    for (int i = 0; i < 8; ++i) mx = fmaxf(mx, fabsf(f[i]));
#pragma unroll
    for (int off = 16; off; off >>= 1)
        mx = fmaxf(mx, __shfl_xor_sync(0xffffffffu, mx, off));

    __shared__ float red[8];
    if ((tid & 31) == 0) red[tid >> 5] = mx;
    __syncthreads();
    float m2 = red[0];
#pragma unroll
    for (int w = 1; w < 8; ++w) m2 = fmaxf(m2, red[w]);

    float s = fmaxf(m2, 1e-20f) / (float)QMAXI;
    if (tid == 0) srow[row] = s;
    float inv = 1.0f / s;

    char o1[8], o2[8];
#pragma unroll
    for (int i = 0; i < 8; ++i) {
        int q = __float2int_rn(f[i] * inv);
        q = max(-QMAXI, min(QMAXI, q));
        int a1 = (q + 64) >> 7;          // arithmetic shift
        o1[i] = (char)a1;
        o2[i] = (char)(q - (a1 << 7));   // in [-64, 63]
    }
    *(uint2*)(q1 + (size_t)row * GK + tid * 8) = *(uint2*)o1;
    *(uint2*)(q2 + (size_t)row * GK + tid * 8) = *(uint2*)o2;
}

// ---------------------------------------------------------------------------
// ALL weight transposes fused: fp32 [GK,N] -> fp32 [N,GK] (quant input).
// y-tiles 0..63 -> Wq, 64..79 -> Wk, 80..95 -> Wv, 96..159 -> Wo.
// ---------------------------------------------------------------------------
__global__ void wtrans_all(const float* __restrict__ Wq, const float* __restrict__ Wk,
                           const float* __restrict__ Wv, const float* __restrict__ Wo,
                           float* __restrict__ wt, float* __restrict__ wot)
{
    __shared__ float t[32][33];
    const int yb = blockIdx.y;
    const float* in;
    float* outp;
    int N, nt;
    if (yb < 64)       { in = Wq; outp = wt;                            N = EMB;   nt = yb; }
    else if (yb < 80)  { in = Wk; outp = wt + (size_t)EMB * GK;         N = KVDIM; nt = yb - 64; }
    else if (yb < 96)  { in = Wv; outp = wt + (size_t)(EMB+KVDIM) * GK; N = KVDIM; nt = yb - 80; }
    else               { in = Wo; outp = wot;                           N = EMB;   nt = yb - 96; }

    const int n0 = nt * 32;
    const int k0 = blockIdx.x * 32;
    const int tx = threadIdx.x, ty = threadIdx.y;
#pragma unroll
    for (int i = 0; i < 4; ++i) {
        int k = k0 + ty + i * 8;
        t[ty + i * 8][tx] = in[(size_t)k * N + n0 + tx];
    }
    __syncthreads();
#pragma unroll
    for (int i = 0; i < 4; ++i) {
        int n = n0 + ty + i * 8;
        outp[(size_t)n * GK + k0 + tx] = t[tx][ty + i * 8];
    }
}

// ---------------------------------------------------------------------------
// V transpose: fp32 V[B,S,KVDIM] -> bf16 hi/lo Vt[B,G,HDIM,SEQ]
// ---------------------------------------------------------------------------
__global__ void vtrans_hilo(const float* __restrict__ V,
                            __nv_bfloat16* __restrict__ oh,
                            __nv_bfloat16* __restrict__ ol)
{
    __shared__ float t[32][33];
    int s0 = blockIdx.x * 32;
    int d0 = blockIdx.y * 32;
    int b  = blockIdx.z;
    int tx = threadIdx.x, ty = threadIdx.y;
#pragma unroll
    for (int i = 0; i < 4; ++i) {
        int s = s0 + ty + i * 8;
        t[ty + i * 8][tx] = V[((size_t)b * SEQ + s) * KVDIM + d0 + tx];
    }
    __syncthreads();
#pragma unroll
    for (int i = 0; i < 4; ++i) {
        int d = d0 + ty + i * 8;
        int g = d >> 6, dd = d & 63;
        float v = t[tx][ty + i * 8];
        __nv_bfloat16 h = __float2bfloat16(v);
        __nv_bfloat16 l = __float2bfloat16(v - __bfloat162float(h));
        size_t o = (((size_t)b * NGROUPS + g) * HDIM + dd) * SEQ + s0 + tx;
        oh[o] = h;
        ol[o] = l;
    }
}

// ---------------------------------------------------------------------------
// int8 IMMA GEMM (m16n8k32), 2-digit split, exact s32 accumulation.
//   C = sA_i * sB_j * (16384*P11 + 128*(P12 + P21))
// PART=0: acc = A1@B1^T over 64 k-steps; writes Cp = 16384*(float)acc.
// PART=1: acc = A1@B2^T + A2@B1^T over 128 k-steps; final epilogue:
//   MODE=0: out = sA*sB*(Cp + 128*acc) + bias  (fp32)
//   MODE=1: QKV routing: q -> bf16 hi/lo *0.125 ; k -> bf16 hi/lo ; v -> fp32
// CTA tile 128x256, BKK=32 int8, 4-stage cp.async, 8 warps (2x4), 64x64/warp.
// ---------------------------------------------------------------------------
#define ISTR   48                       // smem bytes per row (16B mult, cf-free)
#define IB_OFF (128 * ISTR)             // 6144
#define ISTAGE ((128 + 256) * ISTR)     // 18432
#define SMEM_I8 (4 * ISTAGE)            // 73728

template <int PART, int MODE>
__global__ __launch_bounds__(256)
void gemm_i8(const int8_t* __restrict__ A1, const int8_t* __restrict__ A2,
             const int8_t* __restrict__ B1, const int8_t* __restrict__ B2,
             const float* __restrict__ sAr, const float* __restrict__ sBr,
             float* __restrict__ Cp, int N,
             const float* __restrict__ bias, float* __restrict__ Cout,
             __nv_bfloat16* __restrict__ qh, __nv_bfloat16* __restrict__ ql,
             __nv_bfloat16* __restrict__ kh, __nv_bfloat16* __restrict__ kl,
             float* __restrict__ vf)
{
    extern __shared__ int8_t ism[];
    const int tid  = threadIdx.x;
    const int wid  = tid >> 5;
    const int lane = tid & 31;
    const int m0   = blockIdx.y * 128;
    const int n0   = blockIdx.x * 256;
    const int wm0  = (wid & 1) * 64;
    const int wn0  = (wid >> 1) * 64;
    const uint32_t sbase = smem_u32(ism);

    int acc[4][8][4];
#pragma unroll
    for (int i = 0; i < 4; ++i)
#pragma unroll
        for (int j = 0; j < 8; ++j)
#pragma unroll
            for (int k = 0; k < 4; ++k) acc[i][j][k] = 0;

    const int8_t* Aop[2];
    const int8_t* Bop[2];
    if (PART == 0) { Aop[0] = A1; Bop[0] = B1; Aop[1] = A1; Bop[1] = B1; }
    else           { Aop[0] = A1; Bop[0] = B2; Aop[1] = A2; Bop[1] = B1; }
    const int NSTEPS = (PART == 0) ? 64 : 128;

    const int lr = tid >> 1;            // 0..127
    const int lc = (tid & 1) * 16;      // 16B chunk

    auto issue = [&](int t, int buf) {
        int ph = t >> 6;                // 0 or 1
        int k0 = (t & 63) * 32;
        uint32_t sd = sbase + (uint32_t)buf * ISTAGE;
        cp16(sd + lr * ISTR + lc,                   Aop[ph] + (size_t)(m0 + lr) * GK + k0 + lc);
        cp16(sd + IB_OFF + lr * ISTR + lc,          Bop[ph] + (size_t)(n0 + lr) * GK + k0 + lc);
        cp16(sd + IB_OFF + (lr + 128) * ISTR + lc,  Bop[ph] + (size_t)(n0 + lr + 128) * GK + k0 + lc);
    };

    // ldmatrix byte addressing (s8 m16n8k32 fragments == 16 rows x 32B tiles)
    const int aRow = lane & 15;
    const int aKb  = (lane >> 4) * 16;
    const int bRow = (lane & 7) | ((lane & 16) >> 1);
    const int bKb  = (lane & 8) * 2;

#pragma unroll
    for (int s = 0; s < 3; ++s) { issue(s, s); CP_COMMIT(); }

    for (int t = 0; t < NSTEPS; ++t) {
        CP_WAIT2();
        __syncthreads();
        if (t + 3 < NSTEPS) issue(t + 3, (t + 3) & 3);
        CP_COMMIT();

        const uint32_t sA_ = sbase + (uint32_t)(t & 3) * ISTAGE;
        const uint32_t sB_ = sA_ + IB_OFF;

        uint32_t af[4][4], bf[4][4];
#pragma unroll
        for (int mt = 0; mt < 4; ++mt)
            ldmx4(sA_ + (uint32_t)((wm0 + mt * 16 + aRow) * ISTR + aKb),
                  af[mt][0], af[mt][1], af[mt][2], af[mt][3]);
#pragma unroll
        for (int nb = 0; nb < 4; ++nb)
            ldmx4(sB_ + (uint32_t)((wn0 + nb * 16 + bRow) * ISTR + bKb),
                  bf[nb][0], bf[nb][1], bf[nb][2], bf[nb][3]);
#pragma unroll
        for (int nb = 0; nb < 4; ++nb)
#pragma unroll
            for (int mt = 0; mt < 4; ++mt) {
                imma16832(acc[mt][2 * nb + 0], af[mt], bf[nb][0], bf[nb][1]);
                imma16832(acc[mt][2 * nb + 1], af[mt], bf[nb][2], bf[nb][3]);
            }
    }

    // ---------------- epilogue ----------------
    const int g  = lane >> 2;
    const int tq = lane & 3;

    if (PART == 0) {
#pragma unroll
        for (int mt = 0; mt < 4; ++mt) {
#pragma unroll
            for (int n8 = 0; n8 < 8; ++n8) {
                int r  = m0 + wm0 + mt * 16 + g;
                int gc = n0 + wn0 + n8 * 8 + tq * 2;
                float2 v0 = make_float2(16384.0f * (float)acc[mt][n8][0],
                                        16384.0f * (float)acc[mt][n8][1]);
                float2 v1 = make_float2(16384.0f * (float)acc[mt][n8][2],
                                        16384.0f * (float)acc[mt][n8][3]);
                *(float2*)(Cp + (size_t)r * N + gc)       = v0;
                *(float2*)(Cp + (size_t)(r + 8) * N + gc) = v1;
            }
        }
    } else {
        // region routing constants (MODE==1); BN=256 never straddles 2048/2560
        __nv_bfloat16 *oh = nullptr, *ol = nullptr;
        float qscale = 1.0f;
        int colbase = 0, outw = 0;
        bool isf32 = false;
        if (MODE == 1) {
            if (n0 < EMB)              { oh = qh; ol = ql; colbase = 0;           outw = EMB;   qscale = 0.125f; }
            else if (n0 < EMB + KVDIM) { oh = kh; ol = kl; colbase = EMB;         outw = KVDIM; }
            else                       { isf32 = true;     colbase = EMB + KVDIM; outw = KVDIM; }
        }

#pragma unroll
        for (int mt = 0; mt < 4; ++mt) {
            int r = m0 + wm0 + mt * 16 + g;
            float sr0 = sAr[r], sr1 = sAr[r + 8];
#pragma unroll
            for (int n8 = 0; n8 < 8; ++n8) {
                int gc = n0 + wn0 + n8 * 8 + tq * 2;
                float sc0 = sBr[gc], sc1 = sBr[gc + 1];
                float p00 = Cp[(size_t)r * N + gc],       p01 = Cp[(size_t)r * N + gc + 1];
                float p10 = Cp[(size_t)(r + 8) * N + gc], p11 = Cp[(size_t)(r + 8) * N + gc + 1];
                float v00 = sr0 * sc0 * (p00 + 128.0f * (float)acc[mt][n8][0]);
                float v01 = sr0 * sc1 * (p01 + 128.0f * (float)acc[mt][n8][1]);
                float v10 = sr1 * sc0 * (p10 + 128.0f * (float)acc[mt][n8][2]);
                float v11 = sr1 * sc1 * (p11 + 128.0f * (float)acc[mt][n8][3]);

                if (MODE == 0) {
                    float2 bv = *(const float2*)(bias + gc);
                    *(float2*)(Cout + (size_t)r * N + gc)       = make_float2(v00 + bv.x, v01 + bv.y);
                    *(float2*)(Cout + (size_t)(r + 8) * N + gc) = make_float2(v10 + bv.x, v11 + bv.y);
                } else {
                    int cc = gc - colbase;
                    if (isf32) {
                        *(float2*)(vf + (size_t)r * outw + cc)       = make_float2(v00, v01);
                        *(float2*)(vf + (size_t)(r + 8) * outw + cc) = make_float2(v10, v11);
                    } else {
                        v00 *= qscale; v01 *= qscale; v10 *= qscale; v11 *= qscale;
                        *(uint32_t*)(oh + (size_t)r * outw + cc)       = hilo_h(v00, v01);
                        *(uint32_t*)(ol + (size_t)r * outw + cc)       = hilo_l(v00, v01);
                        *(uint32_t*)(oh + (size_t)(r + 8) * outw + cc) = hilo_h(v10, v11);
                        *(uint32_t*)(ol + (size_t)(r + 8) * outw + cc) = hilo_l(v10, v11);
                    }
                }
            }
        }
    }
}

// ---------------------------------------------------------------------------
// Flash attention on HMMA (causal, GQA rep=4), 3-term bf16 hi/lo split.
// LPT: heavy q-tiles launch first. Writes fp32 attn output.
// ---------------------------------------------------------------------------
#define FSTR  72
#define FSUB  (64 * FSTR)
#define FSTAGE (4 * FSUB)

__global__ __launch_bounds__(256)
void flash_hmma(const __nv_bfloat16* __restrict__ Qh, const __nv_bfloat16* __restrict__ Ql,
                const __nv_bfloat16* __restrict__ Kh, const __nv_bfloat16* __restrict__ Kl,
                const __nv_bfloat16* __restrict__ Vh, const __nv_bfloat16* __restrict__ Vl,
                float* __restrict__ Ab)
{
    extern __shared__ __nv_bfloat16 fs[];

    const int qt = (int)gridDim.x - 1 - (int)blockIdx.x;   // LPT: heavy first
    const int h  = blockIdx.y;
    const int b  = blockIdx.z;
    const int g  = h >> 2;
    const int tid = threadIdx.x, wid = tid >> 5, lane = tid & 31;
    const int q0 = qt * 128;
    const uint32_t sbase = smem_u32(fs);

    const int aRow = lane & 15;
    const int aK   = ((lane >> 4) & 1) * 8;
    const int bRow = (lane & 7) | ((lane & 16) >> 1);
    const int bK   = lane & 8;

    {
        const __nv_bfloat16* qhp = Qh + ((size_t)b * SEQ + q0) * EMB + h * HDIM;
        const __nv_bfloat16* qlp = Ql + ((size_t)b * SEQ + q0) * EMB + h * HDIM;
#pragma unroll
        for (int i = 0; i < 4; ++i) {
            int id = i * 256 + tid;
            int r = id >> 3, c = id & 7;
            *(uint4*)(fs + r * FSTR + c * 8) =
                *(const uint4*)(qhp + (size_t)r * EMB + c * 8);
            *(uint4*)(fs + 128 * FSTR + r * FSTR + c * 8) =
                *(const uint4*)(qlp + (size_t)r * EMB + c * 8);
        }
    }
    __syncthreads();
    uint32_t qhf[4][4], qlf[4][4];
#pragma unroll
    for (int kk = 0; kk < 4; ++kk) {
        ldmx4(sbase + (uint32_t)(((16 * wid + aRow) * FSTR + kk * 16 + aK) * 2),
              qhf[kk][0], qhf[kk][1], qhf[kk][2], qhf[kk][3]);
        ldmx4(sbase + (uint32_t)((128 * FSTR + (16 * wid + aRow) * FSTR + kk * 16 + aK) * 2),
              qlf[kk][0], qlf[kk][1], qlf[kk][2], qlf[kk][3]);
    }
    __syncthreads();

    float oacc[8][4];
#pragma unroll
    for (int j = 0; j < 8; ++j)
#pragma unroll
        for (int k = 0; k < 4; ++k) oacc[j][k] = 0.0f;
    float m0v = -INFINITY, m1v = -INFINITY, l0v = 0.0f, l1v = 0.0f;

    const __nv_bfloat16* khg = Kh + (size_t)b * SEQ * KVDIM + g * HDIM;
    const __nv_bfloat16* klg = Kl + (size_t)b * SEQ * KVDIM + g * HDIM;
    const __nv_bfloat16* vhg = Vh + ((size_t)b * NGROUPS + g) * HDIM * SEQ;
    const __nv_bfloat16* vlg = Vl + ((size_t)b * NGROUPS + g) * HDIM * SEQ;

    const int jrow = tid >> 2;
    const int cch  = tid & 3;

    uint4 pkh[2], pkl[2], pvh[2], pvl[2];
    auto prefetch = [&](int k0) {
#pragma unroll
        for (int i = 0; i < 2; ++i) {
            int c = cch + i * 4;
            pkh[i] = *(const uint4*)(khg + (size_t)(k0 + jrow) * KVDIM + c * 8);
            pkl[i] = *(const uint4*)(klg + (size_t)(k0 + jrow) * KVDIM + c * 8);
            pvh[i] = *(const uint4*)(vhg + (size_t)jrow * SEQ + k0 + c * 8);
            pvl[i] = *(const uint4*)(vlg + (size_t)jrow * SEQ + k0 + c * 8);
        }
    };
    auto commit = [&](int buf) {
        __nv_bfloat16* d = fs + buf * FSTAGE;
#pragma unroll
        for (int i = 0; i < 2; ++i) {
            int c = cch + i * 4;
            *(uint4*)(d + jrow * FSTR + c * 8)            = pkh[i];
            *(uint4*)(d + FSUB + jrow * FSTR + c * 8)     = pkl[i];
            *(uint4*)(d + 2 * FSUB + jrow * FSTR + c * 8) = pvh[i];
            *(uint4*)(d + 3 * FSUB + jrow * FSTR + c * 8) = pvl[i];
        }
    };

    const int nkt = 2 * qt + 2;
    prefetch(0);
    commit(0);
    __syncthreads();

    for (int kt = 0; kt < nkt; ++kt) {
        const int k0 = kt * 64;
        const int cur = kt & 1;
        if (kt + 1 < nkt) prefetch((kt + 1) * 64);

        const bool active = (k0 <= q0 + 16 * wid + 15);
        if (active) {
            const uint32_t khB = sbase + (uint32_t)(cur * FSTAGE * 2);
            const uint32_t klB = khB + FSUB * 2;
            const uint32_t vhB = khB + 2 * FSUB * 2;
            const uint32_t vlB = khB + 3 * FSUB * 2;

            float sacc[8][4];
#pragma unroll
            for (int j = 0; j < 8; ++j)
#pragma unroll
                for (int k = 0; k < 4; ++k) sacc[j][k] = 0.0f;

#pragma unroll
            for (int kk = 0; kk < 4; ++kk) {
#pragma unroll
                for (int nt = 0; nt < 4; ++nt) {
                    uint32_t b0, b1, b2, b3, c0, c1, c2, c3;
                    ldmx4(khB + (uint32_t)(((nt * 16 + bRow) * FSTR + kk * 16 + bK) * 2),
                          b0, b1, b2, b3);
                    ldmx4(klB + (uint32_t)(((nt * 16 + bRow) * FSTR + kk * 16 + bK) * 2),
                          c0, c1, c2, c3);
                    mma16816(sacc[2 * nt + 0], qhf[kk], b0, b1);
                    mma16816(sacc[2 * nt + 1], qhf[kk], b2, b3);
                    mma16816(sacc[2 * nt + 0], qlf[kk], b0, b1);
                    mma16816(sacc[2 * nt + 1], qlf[kk], b2, b3);
                    mma16816(sacc[2 * nt + 0], qhf[kk], c0, c1);
                    mma16816(sacc[2 * nt + 1], qhf[kk], c2, c3);
                }
            }

            const int r0 = q0 + 16 * wid + (lane >> 2);
            if (k0 + 63 > q0 + 16 * wid) {
#pragma unroll
                for (int j = 0; j < 8; ++j) {
                    int kc = k0 + j * 8 + (lane & 3) * 2;
                    if (kc     > r0)     sacc[j][0] = -INFINITY;
                    if (kc + 1 > r0)     sacc[j][1] = -INFINITY;
                    if (kc     > r0 + 8) sacc[j][2] = -INFINITY;
                    if (kc + 1 > r0 + 8) sacc[j][3] = -INFINITY;
                }
            }

            float mx0 = -INFINITY, mx1 = -INFINITY;
#pragma unroll
            for (int j = 0; j < 8; ++j) {
                mx0 = fmaxf(mx0, fmaxf(sacc[j][0], sacc[j][1]));
                mx1 = fmaxf(mx1, fmaxf(sacc[j][2], sacc[j][3]));
            }
#pragma unroll
            for (int off = 1; off <= 2; off <<= 1) {
                mx0 = fmaxf(mx0, __shfl_xor_sync(0xffffffffu, mx0, off));
                mx1 = fmaxf(mx1, __shfl_xor_sync(0xffffffffu, mx1, off));
            }
            float mn0 = fmaxf(m0v, mx0), mn1 = fmaxf(m1v, mx1);
            float al0 = __expf(m0v - mn0), al1 = __expf(m1v - mn1);
            m0v = mn0; m1v = mn1;

            uint32_t pah[4][4], pal[4][4];
            float rs0 = 0.0f, rs1 = 0.0f;
#pragma unroll
            for (int t = 0; t < 4; ++t) {
#pragma unroll
                for (int half = 0; half < 2; ++half) {
                    int j = 2 * t + half;
                    float p00 = __expf(sacc[j][0] - mn0);
                    float p01 = __expf(sacc[j][1] - mn0);
                    float p10 = __expf(sacc[j][2] - mn1);
                    float p11 = __expf(sacc[j][3] - mn1);
                    rs0 += p00 + p01;
                    rs1 += p10 + p11;
                    __nv_bfloat16 h00 = __float2bfloat16(p00);
                    __nv_bfloat16 h01 = __float2bfloat16(p01);
                    __nv_bfloat16 h10 = __float2bfloat16(p10);
                    __nv_bfloat16 h11 = __float2bfloat16(p11);
                    pah[t][0 + half * 2] = packbf(h00, h01);
                    pah[t][1 + half * 2] = packbf(h10, h11);
                    pal[t][0 + half * 2] = packbf(
                        __float2bfloat16(p00 - __bfloat162float(h00)),
                        __float2bfloat16(p01 - __bfloat162float(h01)));
                    pal[t][1 + half * 2] = packbf(
                        __float2bfloat16(p10 - __bfloat162float(h10)),
                        __float2bfloat16(p11 - __bfloat162float(h11)));
                }
            }
#pragma unroll
            for (int off = 1; off <= 2; off <<= 1) {
                rs0 += __shfl_xor_sync(0xffffffffu, rs0, off);
                rs1 += __shfl_xor_sync(0xffffffffu, rs1, off);
            }
            l0v = l0v * al0 + rs0;
            l1v = l1v * al1 + rs1;

#pragma unroll
            for (int j = 0; j < 8; ++j) {
                oacc[j][0] *= al0; oacc[j][1] *= al0;
                oacc[j][2] *= al1; oacc[j][3] *= al1;
            }

#pragma unroll
            for (int t = 0; t < 4; ++t) {
#pragma unroll
                for (int nt = 0; nt < 4; ++nt) {
                    uint32_t v0, v1, v2, v3, w0, w1, w2, w3;
                    ldmx4(vhB + (uint32_t)(((nt * 16 + bRow) * FSTR + t * 16 + bK) * 2),
                          v0, v1, v2, v3);
                    ldmx4(vlB + (uint32_t)(((nt * 16 + bRow) * FSTR + t * 16 + bK) * 2),
                          w0, w1, w2, w3);
                    mma16816(oacc[2 * nt + 0], pah[t], v0, v1);
                    mma16816(oacc[2 * nt + 1], pah[t], v2, v3);
                    mma16816(oacc[2 * nt + 0], pal[t], v0, v1);
                    mma16816(oacc[2 * nt + 1], pal[t], v2, v3);
                    mma16816(oacc[2 * nt + 0], pah[t], w0, w1);
                    mma16816(oacc[2 * nt + 1], pah[t], w2, w3);
                }
            }
        }

        if (kt + 1 < nkt) commit((kt + 1) & 1);
        __syncthreads();
    }

    float i0 = 1.0f / l0v, i1 = 1.0f / l1v;
    float* outp = Ab + ((size_t)b * SEQ + q0 + 16 * wid + (lane >> 2)) * EMB + h * HDIM;
#pragma unroll
    for (int j = 0; j < 8; ++j) {
        int col = j * 8 + (lane & 3) * 2;
        *(float2*)(outp + col)           = make_float2(oacc[j][0] * i0, oacc[j][1] * i0);
        *(float2*)(outp + 8 * EMB + col) = make_float2(oacc[j][2] * i1, oacc[j][3] * i1);
    }
}

// ---------------------------------------------------------------------------
// Launch
// ---------------------------------------------------------------------------
extern "C" void kernel_launch(void* const* d_in, const int* in_sizes, int n_in,
                              void* d_out, int out_size)
{
    const float* x  = (const float*)d_in[0];
    const float* Wq = (const float*)d_in[1];
    const float* Wk = (const float*)d_in[2];
    const float* Wv = (const float*)d_in[3];
    const float* Wo = (const float*)d_in[4];
    const float* bo = (const float*)d_in[5];
    float* out = (float*)d_out;

    float *Vp, *Ap, *Wt, *Wot, *Cp;
    cudaGetSymbolAddress((void**)&Vp,  g_V);
    cudaGetSymbolAddress((void**)&Ap,  g_A);
    cudaGetSymbolAddress((void**)&Wt,  g_Wt);
    cudaGetSymbolAddress((void**)&Wot, g_Wot);
    cudaGetSymbolAddress((void**)&Cp,  g_Cp);

    int8_t *xq1, *xq2, *wq1, *wq2, *woq1, *woq2, *aq1, *aq2;
    float *sx, *sw, *swo, *sa;
    cudaGetSymbolAddress((void**)&xq1,  g_xq1);  cudaGetSymbolAddress((void**)&xq2,  g_xq2);
    cudaGetSymbolAddress((void**)&wq1,  g_wq1);  cudaGetSymbolAddress((void**)&wq2,  g_wq2);
    cudaGetSymbolAddress((void**)&woq1, g_woq1); cudaGetSymbolAddress((void**)&woq2, g_woq2);
    cudaGetSymbolAddress((void**)&aq1,  g_aq1);  cudaGetSymbolAddress((void**)&aq2,  g_aq2);
    cudaGetSymbolAddress((void**)&sx,   g_sx);   cudaGetSymbolAddress((void**)&sw,   g_sw);
    cudaGetSymbolAddress((void**)&swo,  g_swo);  cudaGetSymbolAddress((void**)&sa,   g_sa);

    __nv_bfloat16 *qh, *ql, *kh, *kl, *vth, *vtl;
    cudaGetSymbolAddress((void**)&qh,  g_qh);  cudaGetSymbolAddress((void**)&ql,  g_ql);
    cudaGetSymbolAddress((void**)&kh,  g_kh);  cudaGetSymbolAddress((void**)&kl,  g_kl);
    cudaGetSymbolAddress((void**)&vth, g_vth); cudaGetSymbolAddress((void**)&vtl, g_vtl);

    cudaFuncSetAttribute(gemm_i8<0,0>, cudaFuncAttributeMaxDynamicSharedMemorySize, SMEM_I8);
    cudaFuncSetAttribute(gemm_i8<1,0>, cudaFuncAttributeMaxDynamicSharedMemorySize, SMEM_I8);
    cudaFuncSetAttribute(gemm_i8<1,1>, cudaFuncAttributeMaxDynamicSharedMemorySize, SMEM_I8);
    const int SMEM_FLASH = 2 * FSTAGE * 2;     // 73728 B
    cudaFuncSetAttribute(flash_hmma, cudaFuncAttributeMaxDynamicSharedMemorySize, SMEM_FLASH);

    // 1. Quantize x (per-row 2-digit int8)
    quant2<<<ROWS, 256>>>(x, xq1, xq2, sx);
    // 2. Transpose all weights to [N, GK] fp32, then quantize rows
    wtrans_all<<<dim3(GK / 32, 160), dim3(32, 8)>>>(Wq, Wk, Wv, Wo, Wt, Wot);
    quant2<<<NQKV, 256>>>(Wt,  wq1,  wq2,  sw);
    quant2<<<EMB,  256>>>(Wot, woq1, woq2, swo);

    // 3. Fused QKV projection: int8 two-pass
    gemm_i8<0,0><<<dim3(NQKV / 256, ROWS / 128), 256, SMEM_I8>>>(
        xq1, xq2, wq1, wq2, nullptr, nullptr, Cp, NQKV,
        nullptr, nullptr, nullptr, nullptr, nullptr, nullptr, nullptr);
    gemm_i8<1,1><<<dim3(NQKV / 256, ROWS / 128), 256, SMEM_I8>>>(
        xq1, xq2, wq1, wq2, sx, sw, Cp, NQKV,
        nullptr, nullptr, qh, ql, kh, kl, Vp);

    // 4. Transpose V -> bf16 hi/lo [B,G,D,S]
    vtrans_hilo<<<dim3(SEQ / 32, KVDIM / 32, BATCH), dim3(32, 8)>>>(Vp, vth, vtl);

    // 5. Flash attention (HMMA bf16), fp32 out
    flash_hmma<<<dim3(SEQ / 128, NHEADS, BATCH), 256, SMEM_FLASH>>>(
        qh, ql, kh, kl, vth, vtl, Ap);

    // 6. Quantize attn output, then O projection: int8 two-pass + bias
    quant2<<<ROWS, 256>>>(Ap, aq1, aq2, sa);
    gemm_i8<0,0><<<dim3(EMB / 256, ROWS / 128), 256, SMEM_I8>>>(
        aq1, aq2, woq1, woq2, nullptr, nullptr, Cp, EMB,
        nullptr, nullptr, nullptr, nullptr, nullptr, nullptr, nullptr);
    gemm_i8<1,0><<<dim3(EMB / 256, ROWS / 128), 256, SMEM_I8>>>(
        aq1, aq2, woq1, woq2, sa, swo, Cp, EMB,
        bo, out, nullptr, nullptr, nullptr, nullptr, nullptr);
}

// round 17
// speedup vs baseline: 1.9369x; 1.9369x over previous
#include <cuda_runtime.h>
#include <cuda_bf16.h>
#include <cstdint>
#include <math.h>

// Problem constants
#define BATCH   2
#define SEQ     2048
#define EMB     2048
#define NHEADS  32
#define NGROUPS 8
#define HDIM    64
#define KVDIM   (NGROUPS * HDIM)   // 512
#define ROWS    (BATCH * SEQ)      // 4096
#define GK      2048               // reduction dim for all GEMMs
#define NQKV    (EMB + 2 * KVDIM)  // 3072 fused output columns

// ---------------------------------------------------------------------------
// Scratch (no cudaMalloc allowed)
// ---------------------------------------------------------------------------
__device__ float g_V[(size_t)ROWS * KVDIM];     // fp32 V (for transpose)

__device__ __align__(16) __nv_bfloat16 g_xh[(size_t)ROWS * EMB];
__device__ __align__(16) __nv_bfloat16 g_xl[(size_t)ROWS * EMB];
__device__ __align__(16) __nv_bfloat16 g_ah[(size_t)ROWS * EMB];
__device__ __align__(16) __nv_bfloat16 g_al[(size_t)ROWS * EMB];
// Concatenated transposed weights [NQKV, GK] bf16 hi/lo (rows: Wq|Wk|Wv)
__device__ __align__(16) __nv_bfloat16 g_Wth[(size_t)NQKV * GK];
__device__ __align__(16) __nv_bfloat16 g_Wtl[(size_t)NQKV * GK];
__device__ __align__(16) __nv_bfloat16 g_Woh[(size_t)EMB * EMB], g_Wol[(size_t)EMB * EMB];
// flash operands
__device__ __align__(16) __nv_bfloat16 g_qh[(size_t)ROWS * EMB];
__device__ __align__(16) __nv_bfloat16 g_ql[(size_t)ROWS * EMB];
__device__ __align__(16) __nv_bfloat16 g_kh[(size_t)ROWS * KVDIM];
__device__ __align__(16) __nv_bfloat16 g_kl[(size_t)ROWS * KVDIM];
__device__ __align__(16) __nv_bfloat16 g_vth[(size_t)ROWS * KVDIM];
__device__ __align__(16) __nv_bfloat16 g_vtl[(size_t)ROWS * KVDIM];

// ---------------------------------------------------------------------------
// Primitives
// ---------------------------------------------------------------------------
__device__ __forceinline__ uint32_t smem_u32(const void* p) {
    uint32_t a;
    asm("{ .reg .u64 t; cvta.to.shared.u64 t, %1; cvt.u32.u64 %0, t; }"
        : "=r"(a) : "l"(p));
    return a;
}
__device__ __forceinline__ void ldmx4(uint32_t addr, uint32_t& r0, uint32_t& r1,
                                      uint32_t& r2, uint32_t& r3) {
    asm volatile("ldmatrix.sync.aligned.m8n8.x4.shared.b16 {%0,%1,%2,%3}, [%4];"
                 : "=r"(r0), "=r"(r1), "=r"(r2), "=r"(r3) : "r"(addr));
}
__device__ __forceinline__ void mma16816(float* c, const uint32_t* a,
                                         uint32_t b0, uint32_t b1) {
    asm volatile(
        "mma.sync.aligned.m16n8k16.row.col.f32.bf16.bf16.f32 "
        "{%0,%1,%2,%3}, {%4,%5,%6,%7}, {%8,%9}, {%0,%1,%2,%3};"
        : "+f"(c[0]), "+f"(c[1]), "+f"(c[2]), "+f"(c[3])
        : "r"(a[0]), "r"(a[1]), "r"(a[2]), "r"(a[3]), "r"(b0), "r"(b1));
}
__device__ __forceinline__ uint32_t packbf(__nv_bfloat16 a, __nv_bfloat16 b) {
    __nv_bfloat162 t = __halves2bfloat162(a, b);
    return *reinterpret_cast<uint32_t*>(&t);
}
__device__ __forceinline__ uint32_t hilo_h(float x, float y) {
    return packbf(__float2bfloat16(x), __float2bfloat16(y));
}
__device__ __forceinline__ uint32_t hilo_l(float x, float y) {
    __nv_bfloat16 hx = __float2bfloat16(x), hy = __float2bfloat16(y);
    return packbf(__float2bfloat16(x - __bfloat162float(hx)),
                  __float2bfloat16(y - __bfloat162float(hy)));
}
__device__ __forceinline__ void cp16(uint32_t dst, const void* src) {
    asm volatile("cp.async.cg.shared.global [%0], [%1], 16;" :: "r"(dst), "l"(src));
}
#define CP_COMMIT() asm volatile("cp.async.commit_group;" ::: "memory")
#define CP_WAIT2()  asm volatile("cp.async.wait_group 2;" ::: "memory")

// ---------------------------------------------------------------------------
// Conversion: fp32 [R,K] -> bf16 hi/lo [R,K]
// ---------------------------------------------------------------------------
__global__ void convert_hilo(const float* __restrict__ in,
                             __nv_bfloat16* __restrict__ oh,
                             __nv_bfloat16* __restrict__ ol, int n4, float scale)
{
    int idx = blockIdx.x * blockDim.x + threadIdx.x;
    if (idx >= n4) return;
    float4 v = ((const float4*)in)[idx];
    __nv_bfloat16 h[4], l[4];
    float f[4] = {v.x * scale, v.y * scale, v.z * scale, v.w * scale};
#pragma unroll
    for (int i = 0; i < 4; ++i) {
        h[i] = __float2bfloat16(f[i]);
        l[i] = __float2bfloat16(f[i] - __bfloat162float(h[i]));
    }
    ((uint2*)oh)[idx] = *(uint2*)h;
    ((uint2*)ol)[idx] = *(uint2*)l;
}

// ---------------------------------------------------------------------------
// ALL weight transposes fused into one launch.
// grid = (GK/32, 160): y-tiles 0..63 -> Wq, 64..79 -> Wk, 80..95 -> Wv,
// 96..159 -> Wo.  fp32 [GK, N] -> bf16 hi/lo [N, GK] at the right offset.
// ---------------------------------------------------------------------------
__global__ void wtrans_all(const float* __restrict__ Wq, const float* __restrict__ Wk,
                           const float* __restrict__ Wv, const float* __restrict__ Wo,
                           __nv_bfloat16* __restrict__ wth, __nv_bfloat16* __restrict__ wtl,
                           __nv_bfloat16* __restrict__ woh, __nv_bfloat16* __restrict__ wol)
{
    __shared__ float t[32][33];
    const int yb = blockIdx.y;
    const float* in;
    __nv_bfloat16 *oh, *ol;
    int N, nt;
    if (yb < 64)       { in = Wq; oh = wth;                          ol = wtl;                          N = EMB;   nt = yb; }
    else if (yb < 80)  { in = Wk; oh = wth + (size_t)EMB * GK;       ol = wtl + (size_t)EMB * GK;       N = KVDIM; nt = yb - 64; }
    else if (yb < 96)  { in = Wv; oh = wth + (size_t)(EMB+KVDIM)*GK; ol = wtl + (size_t)(EMB+KVDIM)*GK; N = KVDIM; nt = yb - 80; }
    else               { in = Wo; oh = woh;                          ol = wol;                          N = EMB;   nt = yb - 96; }

    const int n0 = nt * 32;
    const int k0 = blockIdx.x * 32;
    const int tx = threadIdx.x, ty = threadIdx.y;
#pragma unroll
    for (int i = 0; i < 4; ++i) {
        int k = k0 + ty + i * 8;
        t[ty + i * 8][tx] = in[(size_t)k * N + n0 + tx];
    }
    __syncthreads();
#pragma unroll
    for (int i = 0; i < 4; ++i) {
        int n = n0 + ty + i * 8;
        float v = t[tx][ty + i * 8];
        __nv_bfloat16 h = __float2bfloat16(v);
        __nv_bfloat16 l = __float2bfloat16(v - __bfloat162float(h));
        oh[(size_t)n * GK + k0 + tx] = h;
        ol[(size_t)n * GK + k0 + tx] = l;
    }
}

// ---------------------------------------------------------------------------
// V transpose: fp32 V[B,S,KVDIM] -> bf16 hi/lo Vt[B,G,HDIM,SEQ]
// ---------------------------------------------------------------------------
__global__ void vtrans_hilo(const float* __restrict__ V,
                            __nv_bfloat16* __restrict__ oh,
                            __nv_bfloat16* __restrict__ ol)
{
    __shared__ float t[32][33];
    int s0 = blockIdx.x * 32;
    int d0 = blockIdx.y * 32;
    int b  = blockIdx.z;
    int tx = threadIdx.x, ty = threadIdx.y;
#pragma unroll
    for (int i = 0; i < 4; ++i) {
        int s = s0 + ty + i * 8;
        t[ty + i * 8][tx] = V[((size_t)b * SEQ + s) * KVDIM + d0 + tx];
    }
    __syncthreads();
#pragma unroll
    for (int i = 0; i < 4; ++i) {
        int d = d0 + ty + i * 8;
        int g = d >> 6, dd = d & 63;
        float v = t[tx][ty + i * 8];
        __nv_bfloat16 h = __float2bfloat16(v);
        __nv_bfloat16 l = __float2bfloat16(v - __bfloat162float(h));
        size_t o = (((size_t)b * NGROUPS + g) * HDIM + dd) * SEQ + s0 + tx;
        oh[o] = h;
        ol[o] = l;
    }
}

// ---------------------------------------------------------------------------
// HMMA GEMM, 3-term hi/lo split, 4-stage cp.async pipeline.
// 512 threads / 16 warps (4x4), warp tile 32x64 -> 4 warps/SMSP for latency.
// QKV=0: C = A@B^T + bias (fp32 out).   QKV=1: fused epilogue routing.
// ---------------------------------------------------------------------------
#define BM 128
#define BN 256
#define BKK 32
#define ASTRIDE 40
#define ABUF (BM * ASTRIDE)
#define BBUF (BN * ASTRIDE)
#define BUFU (ABUF + BBUF)            // 15360 units = 30720 B per stage
#define KSTEPS (GK / BKK)             // 64
#define NT (3 * KSTEPS)               // 192
#define NSTAGE 4
#define SMEM_GEMM (NSTAGE * BUFU * 2) // 122880 B

template <int QKV>
__global__ __launch_bounds__(512)
void gemm_cp(const __nv_bfloat16* __restrict__ Ah, const __nv_bfloat16* __restrict__ Al,
             const __nv_bfloat16* __restrict__ Bh, const __nv_bfloat16* __restrict__ Bl,
             float* __restrict__ C, int N, const float* __restrict__ bias,
             __nv_bfloat16* __restrict__ qh, __nv_bfloat16* __restrict__ ql,
             __nv_bfloat16* __restrict__ kh, __nv_bfloat16* __restrict__ kl,
             float* __restrict__ vf)
{
    extern __shared__ __nv_bfloat16 sm[];

    const int tid  = threadIdx.x;
    const int wid  = tid >> 5;
    const int lane = tid & 31;
    const int m0   = blockIdx.y * BM;
    const int n0   = blockIdx.x * BN;
    const int wm0  = (wid & 3) * 32;      // 4 warp rows of 32
    const int wn0  = (wid >> 2) * 64;     // 4 warp cols of 64

    const __nv_bfloat16* Aop[3] = {Ah, Al, Ah};
    const __nv_bfloat16* Bop[3] = {Bh, Bh, Bl};

    const uint32_t sbase = smem_u32(sm);

    float acc[2][8][4];
#pragma unroll
    for (int i = 0; i < 2; ++i)
#pragma unroll
        for (int j = 0; j < 8; ++j)
#pragma unroll
            for (int k = 0; k < 4; ++k) acc[i][j][k] = 0.0f;

    const int ar = tid >> 2;          // 0..127
    const int ac = tid & 3;           // 16B chunk in 32-elem row

    auto issue = [&](int t, int buf) {
        const int p  = t >> 6;
        const int k0 = (t & (KSTEPS - 1)) * BKK;
        const __nv_bfloat16* A = Aop[p];
        const __nv_bfloat16* B = Bop[p];
        uint32_t sd  = sbase + (uint32_t)buf * (BUFU * 2);
        cp16(sd + (uint32_t)((ar * ASTRIDE + ac * 8) * 2),
             A + (size_t)(m0 + ar) * GK + k0 + ac * 8);
        uint32_t sdb = sd + ABUF * 2;
        cp16(sdb + (uint32_t)((ar * ASTRIDE + ac * 8) * 2),
             B + (size_t)(n0 + ar) * GK + k0 + ac * 8);
        cp16(sdb + (uint32_t)(((ar + 128) * ASTRIDE + ac * 8) * 2),
             B + (size_t)(n0 + ar + 128) * GK + k0 + ac * 8);
    };

    const int aRow = lane & 15;
    const int aK   = ((lane >> 4) & 1) * 8;
    const int bRow = (lane & 7) | ((lane & 16) >> 1);
    const int bK   = lane & 8;

    // prologue: 3 stages in flight
#pragma unroll
    for (int s = 0; s < 3; ++s) { issue(s, s); CP_COMMIT(); }

    for (int t = 0; t < NT; ++t) {
        CP_WAIT2();
        __syncthreads();
        {
            int tn = t + 3;
            if (tn < NT) issue(tn, tn & 3);
            CP_COMMIT();
        }
        const uint32_t sA = sbase + (uint32_t)(t & 3) * (BUFU * 2);
        const uint32_t sB = sA + ABUF * 2;

#pragma unroll
        for (int kk = 0; kk < 2; ++kk) {
            uint32_t a[2][4];
#pragma unroll
            for (int mt = 0; mt < 2; ++mt)
                ldmx4(sA + (uint32_t)(((wm0 + mt * 16 + aRow) * ASTRIDE + kk * 16 + aK) * 2),
                      a[mt][0], a[mt][1], a[mt][2], a[mt][3]);
#pragma unroll
            for (int nt = 0; nt < 4; ++nt) {
                uint32_t b0, b1, b2, b3;
                ldmx4(sB + (uint32_t)(((wn0 + nt * 16 + bRow) * ASTRIDE + kk * 16 + bK) * 2),
                      b0, b1, b2, b3);
#pragma unroll
                for (int mt = 0; mt < 2; ++mt) {
                    mma16816(acc[mt][2 * nt + 0], a[mt], b0, b1);
                    mma16816(acc[mt][2 * nt + 1], a[mt], b2, b3);
                }
            }
        }
    }

    // ---------------- epilogue ----------------
    const int g  = lane >> 2;
    const int tq = lane & 3;

    if (QKV == 0) {
#pragma unroll
        for (int mt = 0; mt < 2; ++mt) {
#pragma unroll
            for (int n8 = 0; n8 < 8; ++n8) {
                int r  = m0 + wm0 + mt * 16 + g;
                int cc = n0 + wn0 + n8 * 8 + tq * 2;
                float2 v0 = make_float2(acc[mt][n8][0], acc[mt][n8][1]);
                float2 v1 = make_float2(acc[mt][n8][2], acc[mt][n8][3]);
                if (bias) {
                    float2 bv = *(const float2*)(bias + cc);
                    v0.x += bv.x; v0.y += bv.y;
                    v1.x += bv.x; v1.y += bv.y;
                }
                *(float2*)(C + (size_t)r * N + cc)       = v0;
                *(float2*)(C + (size_t)(r + 8) * N + cc) = v1;
            }
        }
    } else {
        __nv_bfloat16 *oh, *ol;
        float scale = 1.0f;
        int colbase, outw;
        bool isf32 = false;
        if (n0 < EMB)             { oh = qh; ol = ql; colbase = n0;              outw = EMB;   scale = 0.125f; }
        else if (n0 < EMB + KVDIM){ oh = kh; ol = kl; colbase = n0 - EMB;        outw = KVDIM; }
        else                      { oh = nullptr; ol = nullptr; colbase = n0 - EMB - KVDIM; outw = KVDIM; isf32 = true; }

#pragma unroll
        for (int mt = 0; mt < 2; ++mt) {
#pragma unroll
            for (int n8 = 0; n8 < 8; ++n8) {
                int r  = m0 + wm0 + mt * 16 + g;
                int cc = colbase + wn0 + n8 * 8 + tq * 2;
                float x0 = acc[mt][n8][0] * scale, x1 = acc[mt][n8][1] * scale;
                float y0 = acc[mt][n8][2] * scale, y1 = acc[mt][n8][3] * scale;
                if (isf32) {
                    *(float2*)(vf + (size_t)r * outw + cc)       = make_float2(x0, x1);
                    *(float2*)(vf + (size_t)(r + 8) * outw + cc) = make_float2(y0, y1);
                } else {
                    *(uint32_t*)(oh + (size_t)r * outw + cc)       = hilo_h(x0, x1);
                    *(uint32_t*)(ol + (size_t)r * outw + cc)       = hilo_l(x0, x1);
                    *(uint32_t*)(oh + (size_t)(r + 8) * outw + cc) = hilo_h(y0, y1);
                    *(uint32_t*)(ol + (size_t)(r + 8) * outw + cc) = hilo_l(y0, y1);
                }
            }
        }
    }
}

// ---------------------------------------------------------------------------
// Flash attention on HMMA (causal, GQA rep=4), 3-term hi/lo split.
// (unchanged from R15 pass)
// ---------------------------------------------------------------------------
#define FSTR  72
#define FSUB  (64 * FSTR)
#define FSTAGE (4 * FSUB)

__global__ __launch_bounds__(256)
void flash_hmma(const __nv_bfloat16* __restrict__ Qh, const __nv_bfloat16* __restrict__ Ql,
                const __nv_bfloat16* __restrict__ Kh, const __nv_bfloat16* __restrict__ Kl,
                const __nv_bfloat16* __restrict__ Vh, const __nv_bfloat16* __restrict__ Vl,
                __nv_bfloat16* __restrict__ Aoh, __nv_bfloat16* __restrict__ Aol)
{
    extern __shared__ __nv_bfloat16 fs[];

    const int qt = blockIdx.x;
    const int h  = blockIdx.y;
    const int b  = blockIdx.z;
    const int g  = h >> 2;
    const int tid = threadIdx.x, wid = tid >> 5, lane = tid & 31;
    const int q0 = qt * 128;
    const uint32_t sbase = smem_u32(fs);

    const int aRow = lane & 15;
    const int aK   = ((lane >> 4) & 1) * 8;
    const int bRow = (lane & 7) | ((lane & 16) >> 1);
    const int bK   = lane & 8;

    {
        const __nv_bfloat16* qhp = Qh + ((size_t)b * SEQ + q0) * EMB + h * HDIM;
        const __nv_bfloat16* qlp = Ql + ((size_t)b * SEQ + q0) * EMB + h * HDIM;
#pragma unroll
        for (int i = 0; i < 4; ++i) {
            int id = i * 256 + tid;
            int r = id >> 3, c = id & 7;
            *(uint4*)(fs + r * FSTR + c * 8) =
                *(const uint4*)(qhp + (size_t)r * EMB + c * 8);
            *(uint4*)(fs + 128 * FSTR + r * FSTR + c * 8) =
                *(const uint4*)(qlp + (size_t)r * EMB + c * 8);
        }
    }
    __syncthreads();
    uint32_t qhf[4][4], qlf[4][4];
#pragma unroll
    for (int kk = 0; kk < 4; ++kk) {
        ldmx4(sbase + (uint32_t)(((16 * wid + aRow) * FSTR + kk * 16 + aK) * 2),
              qhf[kk][0], qhf[kk][1], qhf[kk][2], qhf[kk][3]);
        ldmx4(sbase + (uint32_t)((128 * FSTR + (16 * wid + aRow) * FSTR + kk * 16 + aK) * 2),
              qlf[kk][0], qlf[kk][1], qlf[kk][2], qlf[kk][3]);
    }
    __syncthreads();

    float oacc[8][4];
#pragma unroll
    for (int j = 0; j < 8; ++j)
#pragma unroll
        for (int k = 0; k < 4; ++k) oacc[j][k] = 0.0f;
    float m0v = -INFINITY, m1v = -INFINITY, l0v = 0.0f, l1v = 0.0f;

    const __nv_bfloat16* khg = Kh + (size_t)b * SEQ * KVDIM + g * HDIM;
    const __nv_bfloat16* klg = Kl + (size_t)b * SEQ * KVDIM + g * HDIM;
    const __nv_bfloat16* vhg = Vh + ((size_t)b * NGROUPS + g) * HDIM * SEQ;
    const __nv_bfloat16* vlg = Vl + ((size_t)b * NGROUPS + g) * HDIM * SEQ;

    const int jrow = tid >> 2;
    const int cch  = tid & 3;

    uint4 pkh[2], pkl[2], pvh[2], pvl[2];
    auto prefetch = [&](int k0) {
#pragma unroll
        for (int i = 0; i < 2; ++i) {
            int c = cch + i * 4;
            pkh[i] = *(const uint4*)(khg + (size_t)(k0 + jrow) * KVDIM + c * 8);
            pkl[i] = *(const uint4*)(klg + (size_t)(k0 + jrow) * KVDIM + c * 8);
            pvh[i] = *(const uint4*)(vhg + (size_t)jrow * SEQ + k0 + c * 8);
            pvl[i] = *(const uint4*)(vlg + (size_t)jrow * SEQ + k0 + c * 8);
        }
    };
    auto commit = [&](int buf) {
        __nv_bfloat16* d = fs + buf * FSTAGE;
#pragma unroll
        for (int i = 0; i < 2; ++i) {
            int c = cch + i * 4;
            *(uint4*)(d + jrow * FSTR + c * 8)            = pkh[i];
            *(uint4*)(d + FSUB + jrow * FSTR + c * 8)     = pkl[i];
            *(uint4*)(d + 2 * FSUB + jrow * FSTR + c * 8) = pvh[i];
            *(uint4*)(d + 3 * FSUB + jrow * FSTR + c * 8) = pvl[i];
        }
    };

    const int nkt = 2 * qt + 2;
    prefetch(0);
    commit(0);
    __syncthreads();

    for (int kt = 0; kt < nkt; ++kt) {
        const int k0 = kt * 64;
        const int cur = kt & 1;
        if (kt + 1 < nkt) prefetch((kt + 1) * 64);

        const bool active = (k0 <= q0 + 16 * wid + 15);
        if (active) {
            const uint32_t khB = sbase + (uint32_t)(cur * FSTAGE * 2);
            const uint32_t klB = khB + FSUB * 2;
            const uint32_t vhB = khB + 2 * FSUB * 2;
            const uint32_t vlB = khB + 3 * FSUB * 2;

            float sacc[8][4];
#pragma unroll
            for (int j = 0; j < 8; ++j)
#pragma unroll
                for (int k = 0; k < 4; ++k) sacc[j][k] = 0.0f;

#pragma unroll
            for (int kk = 0; kk < 4; ++kk) {
#pragma unroll
                for (int nt = 0; nt < 4; ++nt) {
                    uint32_t b0, b1, b2, b3, c0, c1, c2, c3;
                    ldmx4(khB + (uint32_t)(((nt * 16 + bRow) * FSTR + kk * 16 + bK) * 2),
                          b0, b1, b2, b3);
                    ldmx4(klB + (uint32_t)(((nt * 16 + bRow) * FSTR + kk * 16 + bK) * 2),
                          c0, c1, c2, c3);
                    mma16816(sacc[2 * nt + 0], qhf[kk], b0, b1);
                    mma16816(sacc[2 * nt + 1], qhf[kk], b2, b3);
                    mma16816(sacc[2 * nt + 0], qlf[kk], b0, b1);
                    mma16816(sacc[2 * nt + 1], qlf[kk], b2, b3);
                    mma16816(sacc[2 * nt + 0], qhf[kk], c0, c1);
                    mma16816(sacc[2 * nt + 1], qhf[kk], c2, c3);
                }
            }

            const int r0 = q0 + 16 * wid + (lane >> 2);
            if (k0 + 63 > q0 + 16 * wid) {
#pragma unroll
                for (int j = 0; j < 8; ++j) {
                    int kc = k0 + j * 8 + (lane & 3) * 2;
                    if (kc     > r0)     sacc[j][0] = -INFINITY;
                    if (kc + 1 > r0)     sacc[j][1] = -INFINITY;
                    if (kc     > r0 + 8) sacc[j][2] = -INFINITY;
                    if (kc + 1 > r0 + 8) sacc[j][3] = -INFINITY;
                }
            }

            float mx0 = -INFINITY, mx1 = -INFINITY;
#pragma unroll
            for (int j = 0; j < 8; ++j) {
                mx0 = fmaxf(mx0, fmaxf(sacc[j][0], sacc[j][1]));
                mx1 = fmaxf(mx1, fmaxf(sacc[j][2], sacc[j][3]));
            }
#pragma unroll
            for (int off = 1; off <= 2; off <<= 1) {
                mx0 = fmaxf(mx0, __shfl_xor_sync(0xffffffffu, mx0, off));
                mx1 = fmaxf(mx1, __shfl_xor_sync(0xffffffffu, mx1, off));
            }
            float mn0 = fmaxf(m0v, mx0), mn1 = fmaxf(m1v, mx1);
            float al0 = __expf(m0v - mn0), al1 = __expf(m1v - mn1);
            m0v = mn0; m1v = mn1;

            uint32_t pah[4][4], pal[4][4];
            float rs0 = 0.0f, rs1 = 0.0f;
#pragma unroll
            for (int t = 0; t < 4; ++t) {
#pragma unroll
                for (int half = 0; half < 2; ++half) {
                    int j = 2 * t + half;
                    float p00 = __expf(sacc[j][0] - mn0);
                    float p01 = __expf(sacc[j][1] - mn0);
                    float p10 = __expf(sacc[j][2] - mn1);
                    float p11 = __expf(sacc[j][3] - mn1);
                    rs0 += p00 + p01;
                    rs1 += p10 + p11;
                    __nv_bfloat16 h00 = __float2bfloat16(p00);
                    __nv_bfloat16 h01 = __float2bfloat16(p01);
                    __nv_bfloat16 h10 = __float2bfloat16(p10);
                    __nv_bfloat16 h11 = __float2bfloat16(p11);
                    pah[t][0 + half * 2] = packbf(h00, h01);
                    pah[t][1 + half * 2] = packbf(h10, h11);
                    pal[t][0 + half * 2] = packbf(
                        __float2bfloat16(p00 - __bfloat162float(h00)),
                        __float2bfloat16(p01 - __bfloat162float(h01)));
                    pal[t][1 + half * 2] = packbf(
                        __float2bfloat16(p10 - __bfloat162float(h10)),
                        __float2bfloat16(p11 - __bfloat162float(h11)));
                }
            }
#pragma unroll
            for (int off = 1; off <= 2; off <<= 1) {
                rs0 += __shfl_xor_sync(0xffffffffu, rs0, off);
                rs1 += __shfl_xor_sync(0xffffffffu, rs1, off);
            }
            l0v = l0v * al0 + rs0;
            l1v = l1v * al1 + rs1;

#pragma unroll
            for (int j = 0; j < 8; ++j) {
                oacc[j][0] *= al0; oacc[j][1] *= al0;
                oacc[j][2] *= al1; oacc[j][3] *= al1;
            }

#pragma unroll
            for (int t = 0; t < 4; ++t) {
#pragma unroll
                for (int nt = 0; nt < 4; ++nt) {
                    uint32_t v0, v1, v2, v3, w0, w1, w2, w3;
                    ldmx4(vhB + (uint32_t)(((nt * 16 + bRow) * FSTR + t * 16 + bK) * 2),
                          v0, v1, v2, v3);
                    ldmx4(vlB + (uint32_t)(((nt * 16 + bRow) * FSTR + t * 16 + bK) * 2),
                          w0, w1, w2, w3);
                    mma16816(oacc[2 * nt + 0], pah[t], v0, v1);
                    mma16816(oacc[2 * nt + 1], pah[t], v2, v3);
                    mma16816(oacc[2 * nt + 0], pal[t], v0, v1);
                    mma16816(oacc[2 * nt + 1], pal[t], v2, v3);
                    mma16816(oacc[2 * nt + 0], pah[t], w0, w1);
                    mma16816(oacc[2 * nt + 1], pah[t], w2, w3);
                }
            }
        }

        if (kt + 1 < nkt) commit((kt + 1) & 1);
        __syncthreads();
    }

    float i0 = 1.0f / l0v, i1 = 1.0f / l1v;
    size_t rowoff = ((size_t)b * SEQ + q0 + 16 * wid + (lane >> 2)) * EMB + h * HDIM;
    __nv_bfloat16* oh = Aoh + rowoff;
    __nv_bfloat16* ol = Aol + rowoff;
#pragma unroll
    for (int j = 0; j < 8; ++j) {
        int col = j * 8 + (lane & 3) * 2;
        float x0 = oacc[j][0] * i0, x1 = oacc[j][1] * i0;
        float y0 = oacc[j][2] * i1, y1 = oacc[j][3] * i1;
        *(uint32_t*)(oh + col)           = hilo_h(x0, x1);
        *(uint32_t*)(ol + col)           = hilo_l(x0, x1);
        *(uint32_t*)(oh + 8 * EMB + col) = hilo_h(y0, y1);
        *(uint32_t*)(ol + 8 * EMB + col) = hilo_l(y0, y1);
    }
}

// ---------------------------------------------------------------------------
// Launch
// ---------------------------------------------------------------------------
extern "C" void kernel_launch(void* const* d_in, const int* in_sizes, int n_in,
                              void* d_out, int out_size)
{
    const float* x  = (const float*)d_in[0];
    const float* Wq = (const float*)d_in[1];
    const float* Wk = (const float*)d_in[2];
    const float* Wv = (const float*)d_in[3];
    const float* Wo = (const float*)d_in[4];
    const float* bo = (const float*)d_in[5];
    float* out = (float*)d_out;

    float* Vp;
    cudaGetSymbolAddress((void**)&Vp, g_V);

    __nv_bfloat16 *xh, *xl, *ah, *al, *wth, *wtl, *woh, *wol;
    __nv_bfloat16 *qh, *ql, *kh, *kl, *vth, *vtl;
    cudaGetSymbolAddress((void**)&xh, g_xh);   cudaGetSymbolAddress((void**)&xl, g_xl);
    cudaGetSymbolAddress((void**)&ah, g_ah);   cudaGetSymbolAddress((void**)&al, g_al);
    cudaGetSymbolAddress((void**)&wth, g_Wth); cudaGetSymbolAddress((void**)&wtl, g_Wtl);
    cudaGetSymbolAddress((void**)&woh, g_Woh); cudaGetSymbolAddress((void**)&wol, g_Wol);
    cudaGetSymbolAddress((void**)&qh, g_qh);   cudaGetSymbolAddress((void**)&ql, g_ql);
    cudaGetSymbolAddress((void**)&kh, g_kh);   cudaGetSymbolAddress((void**)&kl, g_kl);
    cudaGetSymbolAddress((void**)&vth, g_vth); cudaGetSymbolAddress((void**)&vtl, g_vtl);

    cudaFuncSetAttribute(gemm_cp<0>, cudaFuncAttributeMaxDynamicSharedMemorySize, SMEM_GEMM);
    cudaFuncSetAttribute(gemm_cp<1>, cudaFuncAttributeMaxDynamicSharedMemorySize, SMEM_GEMM);
    const int SMEM_FLASH = 2 * FSTAGE * 2;     // 73728 B
    cudaFuncSetAttribute(flash_hmma, cudaFuncAttributeMaxDynamicSharedMemorySize, SMEM_FLASH);

    // 1. Convert x -> bf16 hi/lo
    {
        int n4 = ROWS * EMB / 4;
        convert_hilo<<<(n4 + 255) / 256, 256>>>(x, xh, xl, n4, 1.0f);
    }
    // 2. ALL weight transposes in one launch
    wtrans_all<<<dim3(GK / 32, 160), dim3(32, 8)>>>(Wq, Wk, Wv, Wo, wth, wtl, woh, wol);

    // 3. Fused QKV projection (epilogue writes qh/ql x0.125, kh/kl, fp32 V)
    gemm_cp<1><<<dim3(NQKV / BN, ROWS / BM), 512, SMEM_GEMM>>>(
        xh, xl, wth, wtl, nullptr, 0, nullptr, qh, ql, kh, kl, Vp);

    // 4. Transpose V -> bf16 hi/lo [B,G,D,S]
    vtrans_hilo<<<dim3(SEQ / 32, KVDIM / 32, BATCH), dim3(32, 8)>>>(Vp, vth, vtl);

    // 5. Flash attention (HMMA), writes ah/al directly
    flash_hmma<<<dim3(SEQ / 128, NHEADS, BATCH), 256, SMEM_FLASH>>>(
        qh, ql, kh, kl, vth, vtl, ah, al);

    // 6. Output projection + bias
    gemm_cp<0><<<dim3(EMB / BN, ROWS / BM), 512, SMEM_GEMM>>>(
        ah, al, woh, wol, out, EMB, bo, nullptr, nullptr, nullptr, nullptr, nullptr);
}